// round 2
// baseline (speedup 1.0000x reference)
#include <cuda_runtime.h>

// Problem constants
#define NQ   20
#define NL   8
#define BB   32
#define DIM  (1u << NQ)        // 1048576
#define NF4  (DIM / 4)         // 262144 float4s per statevector
#define TPB  256

// K2 geometry: 32 chunks x 8 batch-groups (4 batches each) = 256 blocks
#define CHUNKS 32
#define BPG 4                          // batches per block
#define F4_PER_CHUNK (NF4 / CHUNKS)    // 8192 float4 per chunk
#define JO 2                           // outer iters (bit 14)
#define JI 16                          // inner iters (bits 10..13); JO*JI*TPB == F4_PER_CHUNK

// K1 geometry: 4 float4 per thread
#define K1U 4
#define K1_GRID (NF4 / (TPB * K1U))    // 256 blocks

// Scratch (static device arrays: no allocation anywhere)
__device__ float g_G[DIM];                               // G[i] = prod_l noise[l,i]^2
__device__ float g_part[CHUNKS * 8 * BPG * 21];          // per-block partials: [block][b4][21]

// ---------------------------------------------------------------------------
// Kernel 1: G[i] = prod over 8 layers of noise[l,i]^2.
// 4 float4 per thread => 32 independent loads in flight. __ldcs keeps the
// streaming noise from polluting L2 (we want G resident there for K2).
// ---------------------------------------------------------------------------
__global__ void __launch_bounds__(TPB) k_prodG(const float* __restrict__ noise) {
    const unsigned base = blockIdx.x * (TPB * K1U) + threadIdx.x;
    const float4* n4 = reinterpret_cast<const float4*>(noise);
    float4 g[K1U];
#pragma unroll
    for (int u = 0; u < K1U; u++) {
        float4 v = __ldcs(n4 + base + u * TPB);
        g[u].x = v.x * v.x; g[u].y = v.y * v.y; g[u].z = v.z * v.z; g[u].w = v.w * v.w;
    }
#pragma unroll
    for (int l = 1; l < NL; l++) {
#pragma unroll
        for (int u = 0; u < K1U; u++) {
            float4 v = __ldcs(n4 + (size_t)l * NF4 + base + u * TPB);
            g[u].x *= v.x * v.x; g[u].y *= v.y * v.y;
            g[u].z *= v.z * v.z; g[u].w *= v.w * v.w;
        }
    }
#pragma unroll
    for (int u = 0; u < K1U; u++)
        reinterpret_cast<float4*>(g_G)[base + u * TPB] = g[u];
}

// ---------------------------------------------------------------------------
// Kernel 2: bit-masked reduction, 4 batches per block (G read once per block).
// Element index i = idx*4 + r;  idx = chunk*8192 + (jo*16+ji)*256 + t.
//   qubits 0,1   <- r          (per-float4 lane position)
//   qubits 2..9  <- t bits     (free: applied at reduction time)
//   qubits 10..13<- ji bits    (compile-time predicated adds)
//   qubit  14    <- jo bit     (compile-time, JO unrolled)
//   qubits 15..19<- chunk bits (free: applied at reduction time)
// ---------------------------------------------------------------------------
__global__ void __launch_bounds__(TPB) k_bitsum(const float* __restrict__ amps) {
    const int bg    = blockIdx.x & 7;        // batch group: batches bg*4 .. bg*4+3
    const int chunk = blockIdx.x >> 3;       // 0..31
    const int t     = threadIdx.x;

    const size_t sliceOff = (size_t)chunk * F4_PER_CHUNK + t;
    const float4* g4 = reinterpret_cast<const float4*>(g_G) + sliceOff;
    const float4* a4[BPG];
#pragma unroll
    for (int b4 = 0; b4 < BPG; b4++)
        a4[b4] = reinterpret_cast<const float4*>(amps)
                 + (size_t)(bg * BPG + b4) * NF4 + sliceOff;

    // per-batch accumulators
    float acc0[BPG], acc1[BPG], accJ0[BPG], accJ1[BPG], accJ2[BPG], accJ3[BPG],
          accO[BPG], accT[BPG];
#pragma unroll
    for (int b4 = 0; b4 < BPG; b4++) {
        acc0[b4] = acc1[b4] = accJ0[b4] = accJ1[b4] = 0.f;
        accJ2[b4] = accJ3[b4] = accO[b4] = accT[b4] = 0.f;
    }

#pragma unroll
    for (int jo = 0; jo < JO; jo++) {
        float sO[BPG] = {0.f, 0.f, 0.f, 0.f};
#pragma unroll
        for (int ji = 0; ji < JI; ji++) {
            const int off = (jo * JI + ji) * TPB;
            float4 g = __ldg(g4 + off);      // hot in L2 (4 MB), shared by 8 blocks
#pragma unroll
            for (int b4 = 0; b4 < BPG; b4++) {
                float4 a = __ldcs(a4[b4] + off);   // streaming, read-once
                float w0 = a.x * a.x * g.x;
                float w1 = a.y * a.y * g.y;
                float w2 = a.z * a.z * g.z;
                float w3 = a.w * a.w * g.w;
                float s  = (w0 + w1) + (w2 + w3);
                acc0[b4] += w1 + w3;               // qubit 0
                acc1[b4] += w2 + w3;               // qubit 1
                if (ji & 1) accJ0[b4] += s;        // qubit 10 (folded at compile time)
                if (ji & 2) accJ1[b4] += s;        // qubit 11
                if (ji & 4) accJ2[b4] += s;        // qubit 12
                if (ji & 8) accJ3[b4] += s;        // qubit 13
                sO[b4] += s;
            }
        }
#pragma unroll
        for (int b4 = 0; b4 < BPG; b4++) {
            if (jo) accO[b4] += sO[b4];            // qubit 14
            accT[b4] += sO[b4];
        }
    }

    __shared__ float red[TPB / 32][BPG][21];
    const int wid = t >> 5, lane = t & 31;

#pragma unroll
    for (int b4 = 0; b4 < BPG; b4++) {
        float vals[21];
        vals[0] = acc0[b4];
        vals[1] = acc1[b4];
#pragma unroll
        for (int k = 0; k < 8; k++) vals[2 + k] = ((t >> k) & 1) ? accT[b4] : 0.f;
        vals[10] = accJ0[b4]; vals[11] = accJ1[b4];
        vals[12] = accJ2[b4]; vals[13] = accJ3[b4];
        vals[14] = accO[b4];
#pragma unroll
        for (int m = 0; m < 5; m++) vals[15 + m] = ((chunk >> m) & 1) ? accT[b4] : 0.f;
        vals[20] = accT[b4];
#pragma unroll
        for (int k = 0; k < 21; k++) {
#pragma unroll
            for (int o = 16; o > 0; o >>= 1)
                vals[k] += __shfl_xor_sync(0xffffffffu, vals[k], o);
        }
        if (lane == 0) {
#pragma unroll
            for (int k = 0; k < 21; k++) red[wid][b4][k] = vals[k];
        }
    }
    __syncthreads();
    if (t < BPG * 21) {
        const int b4 = t / 21, k = t % 21;
        float s = 0.f;
#pragma unroll
        for (int w = 0; w < TPB / 32; w++) s += red[w][b4][k];
        g_part[(size_t)blockIdx.x * (BPG * 21) + t] = s;
    }
}

// ---------------------------------------------------------------------------
// Kernel 3: reduce partials -> qubit probs -> tanh(qp @ Wi + bi)
// ---------------------------------------------------------------------------
__global__ void k_final(const float* __restrict__ Wi, const float* __restrict__ bi,
                        float* __restrict__ out) {
    __shared__ float Q[BB][21];
    const int t = threadIdx.x;
    if (t < BB * 21) {
        const int b = t / 21, k = t % 21;
        const int bg = b >> 2, b4 = b & 3;
        float s = 0.f;
#pragma unroll
        for (int c = 0; c < CHUNKS; c++)
            s += g_part[(size_t)(c * 8 + bg) * (BPG * 21) + b4 * 21 + k];
        Q[b][k] = s;
    }
    __syncthreads();
    if (t < BB * NQ) {
        const int b = t / NQ, j = t % NQ;
        const float inv = 1.f / Q[b][20];
        float acc = bi[j];
#pragma unroll
        for (int q = 0; q < NQ; q++) acc += (Q[b][q] * inv) * Wi[q * NQ + j];
        out[t] = tanhf(acc);
    }
}

// ---------------------------------------------------------------------------
// Launch: 3 graph-capturable kernels, no syncs, no allocations.
// ---------------------------------------------------------------------------
extern "C" void kernel_launch(void* const* d_in, const int* in_sizes, int n_in,
                              void* d_out, int out_size) {
    int i_amps = 7, i_noise = 8, i_Wi = 9, i_bi = 10;
    for (int i = 0; i < n_in; i++) {
        const long sz = in_sizes[i];
        if (sz == (long)BB * (long)DIM)      i_amps  = i;  // 33,554,432
        else if (sz == (long)NL * (long)DIM) i_noise = i;  //  8,388,608
        else if (sz == NQ * NQ)              i_Wi    = i;  // 400
        else if (sz == NQ)                   i_bi    = i;  // 20
    }

    const float* noise = (const float*)d_in[i_noise];
    const float* amps  = (const float*)d_in[i_amps];
    const float* Wi    = (const float*)d_in[i_Wi];
    const float* bi    = (const float*)d_in[i_bi];
    float* out         = (float*)d_out;

    k_prodG <<<K1_GRID, TPB>>>(noise);          // 256 blocks, 32 loads/thread in flight
    k_bitsum<<<CHUNKS * 8, TPB>>>(amps);        // 256 blocks, 4 batches each
    k_final <<<1, BB * 21>>>(Wi, bi, out);      // 672 threads
}

// round 3
// speedup vs baseline: 1.2380x; 1.2380x over previous
#include <cuda_runtime.h>

// Problem constants
#define NQ   20
#define NL   8
#define BB   32
#define DIM  (1u << NQ)        // 1048576
#define NF4  (DIM / 4)         // 262144 float4s per statevector
#define TPB  256

// K2 geometry: 32 chunks x 16 batch-groups (2 batches each) = 512 blocks
#define CHUNKS 32
#define BPG 2                          // batches per block
#define NGRP (BB / BPG)                // 16 batch groups
#define F4_PER_CHUNK (NF4 / CHUNKS)    // 8192 float4 per chunk
#define JO 2                           // outer iters (bit 14)
#define JI 16                          // inner iters (bits 10..13); JO*JI*TPB == F4_PER_CHUNK

// Scratch (static device arrays: no allocation anywhere)
__device__ float g_G[DIM];                                // G[i] = prod_l noise[l,i]^2
__device__ float g_part[CHUNKS * NGRP * BPG * 21];        // per-block partials: [block][b2][21]

// ---------------------------------------------------------------------------
// Kernel 1: G[i] = prod over 8 layers of noise[l,i]^2  (R1 version: 1024
// blocks, 1 float4/thread, occ ~77% — measured 9.0us)
// ---------------------------------------------------------------------------
__global__ void __launch_bounds__(TPB) k_prodG(const float* __restrict__ noise) {
    unsigned i = blockIdx.x * TPB + threadIdx.x;      // float4 index, grid covers NF4 exactly
    const float4* n4 = reinterpret_cast<const float4*>(noise);
    float4 v = n4[i];
    float4 g;
    g.x = v.x * v.x; g.y = v.y * v.y; g.z = v.z * v.z; g.w = v.w * v.w;
#pragma unroll
    for (int l = 1; l < NL; l++) {
        v = n4[(size_t)l * NF4 + i];
        g.x *= v.x * v.x; g.y *= v.y * v.y; g.z *= v.z * v.z; g.w *= v.w * v.w;
    }
    reinterpret_cast<float4*>(g_G)[i] = g;
}

// ---------------------------------------------------------------------------
// Kernel 2: bit-masked reduction, 2 batches per block (G L2 traffic halved
// vs R1, grid kept at 512 blocks = R1 occupancy).
// Element index i = idx*4 + r;  idx = chunk*8192 + (jo*16+ji)*256 + t.
//   qubits 0,1   <- r          (per-float4 lane position)
//   qubits 2..9  <- t bits     (free: applied at reduction time)
//   qubits 10..13<- ji bits    (compile-time predicated adds)
//   qubit  14    <- jo bit     (compile-time, JO unrolled)
//   qubits 15..19<- chunk bits (free: applied at reduction time)
// ---------------------------------------------------------------------------
__global__ void __launch_bounds__(TPB) k_bitsum(const float* __restrict__ amps) {
    const int bg    = blockIdx.x & (NGRP - 1);   // batch group: batches bg*2, bg*2+1
    const int chunk = blockIdx.x >> 4;           // 0..31
    const int t     = threadIdx.x;

    const size_t sliceOff = (size_t)chunk * F4_PER_CHUNK + t;
    const float4* g4 = reinterpret_cast<const float4*>(g_G) + sliceOff;
    const float4* a4_0 = reinterpret_cast<const float4*>(amps)
                         + (size_t)(bg * BPG + 0) * NF4 + sliceOff;
    const float4* a4_1 = reinterpret_cast<const float4*>(amps)
                         + (size_t)(bg * BPG + 1) * NF4 + sliceOff;

    float acc0[BPG] = {0.f, 0.f}, acc1[BPG] = {0.f, 0.f};
    float accJ0[BPG] = {0.f, 0.f}, accJ1[BPG] = {0.f, 0.f};
    float accJ2[BPG] = {0.f, 0.f}, accJ3[BPG] = {0.f, 0.f};
    float accO[BPG] = {0.f, 0.f}, accT[BPG] = {0.f, 0.f};

#pragma unroll
    for (int jo = 0; jo < JO; jo++) {
        float sO[BPG] = {0.f, 0.f};
#pragma unroll
        for (int ji = 0; ji < JI; ji++) {
            const int off = (jo * JI + ji) * TPB;
            float4 g  = __ldg(g4 + off);           // hot in L2, shared by 16 blocks
            float4 a0 = __ldcs(a4_0 + off);        // streaming, read-once
            float4 a1 = __ldcs(a4_1 + off);
#pragma unroll
            for (int b2 = 0; b2 < BPG; b2++) {
                float4 a = b2 ? a1 : a0;
                float w0 = a.x * a.x * g.x;
                float w1 = a.y * a.y * g.y;
                float w2 = a.z * a.z * g.z;
                float w3 = a.w * a.w * g.w;
                float s  = (w0 + w1) + (w2 + w3);
                acc0[b2] += w1 + w3;               // qubit 0
                acc1[b2] += w2 + w3;               // qubit 1
                if (ji & 1) accJ0[b2] += s;        // qubit 10 (folded at compile time)
                if (ji & 2) accJ1[b2] += s;        // qubit 11
                if (ji & 4) accJ2[b2] += s;        // qubit 12
                if (ji & 8) accJ3[b2] += s;        // qubit 13
                sO[b2] += s;
            }
        }
#pragma unroll
        for (int b2 = 0; b2 < BPG; b2++) {
            if (jo) accO[b2] += sO[b2];            // qubit 14
            accT[b2] += sO[b2];
        }
    }

    __shared__ float red[TPB / 32][BPG][21];
    const int wid = t >> 5, lane = t & 31;

#pragma unroll
    for (int b2 = 0; b2 < BPG; b2++) {
        float vals[21];
        vals[0] = acc0[b2];
        vals[1] = acc1[b2];
#pragma unroll
        for (int k = 0; k < 8; k++) vals[2 + k] = ((t >> k) & 1) ? accT[b2] : 0.f;
        vals[10] = accJ0[b2]; vals[11] = accJ1[b2];
        vals[12] = accJ2[b2]; vals[13] = accJ3[b2];
        vals[14] = accO[b2];
#pragma unroll
        for (int m = 0; m < 5; m++) vals[15 + m] = ((chunk >> m) & 1) ? accT[b2] : 0.f;
        vals[20] = accT[b2];
#pragma unroll
        for (int k = 0; k < 21; k++) {
#pragma unroll
            for (int o = 16; o > 0; o >>= 1)
                vals[k] += __shfl_xor_sync(0xffffffffu, vals[k], o);
        }
        if (lane == 0) {
#pragma unroll
            for (int k = 0; k < 21; k++) red[wid][b2][k] = vals[k];
        }
    }
    __syncthreads();
    if (t < BPG * 21) {
        const int b2 = t / 21, k = t % 21;
        float s = 0.f;
#pragma unroll
        for (int w = 0; w < TPB / 32; w++) s += red[w][b2][k];
        g_part[(size_t)blockIdx.x * (BPG * 21) + t] = s;
    }
}

// ---------------------------------------------------------------------------
// Kernel 3: reduce partials -> qubit probs -> tanh(qp @ Wi + bi)
// ---------------------------------------------------------------------------
__global__ void k_final(const float* __restrict__ Wi, const float* __restrict__ bi,
                        float* __restrict__ out) {
    __shared__ float Q[BB][21];
    const int t = threadIdx.x;
    if (t < BB * 21) {
        const int b = t / 21, k = t % 21;
        const int bg = b >> 1, b2 = b & 1;
        float s = 0.f;
#pragma unroll
        for (int c = 0; c < CHUNKS; c++)
            s += g_part[(size_t)(c * NGRP + bg) * (BPG * 21) + b2 * 21 + k];
        Q[b][k] = s;
    }
    __syncthreads();
    if (t < BB * NQ) {
        const int b = t / NQ, j = t % NQ;
        const float inv = 1.f / Q[b][20];
        float acc = bi[j];
#pragma unroll
        for (int q = 0; q < NQ; q++) acc += (Q[b][q] * inv) * Wi[q * NQ + j];
        out[t] = tanhf(acc);
    }
}

// ---------------------------------------------------------------------------
// Launch: 3 graph-capturable kernels, no syncs, no allocations.
// ---------------------------------------------------------------------------
extern "C" void kernel_launch(void* const* d_in, const int* in_sizes, int n_in,
                              void* d_out, int out_size) {
    int i_amps = 7, i_noise = 8, i_Wi = 9, i_bi = 10;
    for (int i = 0; i < n_in; i++) {
        const long sz = in_sizes[i];
        if (sz == (long)BB * (long)DIM)      i_amps  = i;  // 33,554,432
        else if (sz == (long)NL * (long)DIM) i_noise = i;  //  8,388,608
        else if (sz == NQ * NQ)              i_Wi    = i;  // 400
        else if (sz == NQ)                   i_bi    = i;  // 20
    }

    const float* noise = (const float*)d_in[i_noise];
    const float* amps  = (const float*)d_in[i_amps];
    const float* Wi    = (const float*)d_in[i_Wi];
    const float* bi    = (const float*)d_in[i_bi];
    float* out         = (float*)d_out;

    k_prodG <<<NF4 / TPB, TPB>>>(noise);        // 1024 blocks (R1 geometry)
    k_bitsum<<<CHUNKS * NGRP, TPB>>>(amps);     //  512 blocks, 2 batches each
    k_final <<<1, BB * 21>>>(Wi, bi, out);      //  672 threads
}